// round 1
// baseline (speedup 1.0000x reference)
#include <cuda_runtime.h>
#include <math.h>

#define BS 4
#define LQ 12240
#define EMBED 256
#define HEADS 8
#define MTOT (BS * LQ)   // 48960

// ---------------- scratch (no cudaMalloc allowed) ----------------
__device__ float g_v[(size_t)MTOT * 256];     // projected value [b,Lv,H,32]
__device__ float g_off[(size_t)MTOT * 256];   // offsets [b,q,H,L,P,2]
__device__ float g_attn[(size_t)MTOT * 128];  // attn logits [b,q,H,16]
__device__ float g_acc[(size_t)MTOT * 256];   // sampled acc [b,q,H,32]

// ---------------- fp32 tiled GEMM: C = A(MxK) @ B(KxN) + bias ----------------
#define BM 128
#define BN 64
#define BK 16

__global__ __launch_bounds__(256) void gemm_bias_kernel(
    const float* __restrict__ A, const float* __restrict__ B,
    const float* __restrict__ bias, float* __restrict__ C,
    int M, int N, int K)
{
    __shared__ float As[BK][BM + 4];
    __shared__ float Bs[BK][BN];

    const int tid = threadIdx.x;
    const int bm = blockIdx.y * BM;
    const int bn = blockIdx.x * BN;
    const int tm = (tid >> 4) * 8;   // 0..120
    const int tn = (tid & 15) * 4;   // 0..60

    float acc[8][4];
#pragma unroll
    for (int i = 0; i < 8; i++)
#pragma unroll
        for (int j = 0; j < 4; j++) acc[i][j] = 0.f;

    for (int k0 = 0; k0 < K; k0 += BK) {
        // load A tile 128x16 (two float4 per thread), transpose into As[k][m]
#pragma unroll
        for (int r = 0; r < 2; r++) {
            int idx = tid + r * 256;          // 0..511
            int row = idx >> 2;               // 0..127
            int kc = (idx & 3) * 4;           // 0,4,8,12
            int grow = bm + row;
            if (grow >= M) grow = M - 1;      // clamp; C store is guarded
            float4 a = *(const float4*)&A[(size_t)grow * K + k0 + kc];
            As[kc + 0][row] = a.x;
            As[kc + 1][row] = a.y;
            As[kc + 2][row] = a.z;
            As[kc + 3][row] = a.w;
        }
        // load B tile 16x64 (one float4 per thread)
        {
            int row = tid >> 4;               // 0..15
            int col = (tid & 15) * 4;         // 0..60
            *(float4*)&Bs[row][col] = *(const float4*)&B[(size_t)(k0 + row) * N + bn + col];
        }
        __syncthreads();

#pragma unroll
        for (int k = 0; k < BK; k++) {
            float a[8], bf[4];
#pragma unroll
            for (int i = 0; i < 8; i++) a[i] = As[k][tm + i];
#pragma unroll
            for (int j = 0; j < 4; j++) bf[j] = Bs[k][tn + j];
#pragma unroll
            for (int i = 0; i < 8; i++)
#pragma unroll
                for (int j = 0; j < 4; j++) acc[i][j] = fmaf(a[i], bf[j], acc[i][j]);
        }
        __syncthreads();
    }

    float4 bv = *(const float4*)&bias[bn + tn];
#pragma unroll
    for (int i = 0; i < 8; i++) {
        int m = bm + tm + i;
        if (m < M) {
            float4 o;
            o.x = acc[i][0] + bv.x;
            o.y = acc[i][1] + bv.y;
            o.z = acc[i][2] + bv.z;
            o.w = acc[i][3] + bv.w;
            *(float4*)&C[(size_t)m * N + bn + tn] = o;
        }
    }
}

// ---------------- softmax + bilinear sampling ----------------
// one block per (b,q); warp w = head, lane = channel
__global__ __launch_bounds__(256) void sample_kernel(
    const float* __restrict__ refp,   // [BS,LQ,4,2]
    const float* __restrict__ off,    // [BS*LQ, 256]
    const float* __restrict__ logits, // [BS*LQ, 128]
    const float* __restrict__ v,      // [BS,LQ,8,32]
    float* __restrict__ out)          // [BS*LQ, 256]
{
    const int bq = blockIdx.x;
    const int b = bq / LQ;
    const int h = threadIdx.x >> 5;
    const int c = threadIdx.x & 31;

    const int dims[4]  = {96, 48, 24, 12};
    const int start[4] = {0, 9216, 11520, 12096};

    // softmax over the 16 (level,point) logits of this head (redundant per lane, broadcast loads)
    const float* lg = logits + (size_t)bq * 128 + h * 16;
    float wts[16];
    float mx = -1e30f;
#pragma unroll
    for (int j = 0; j < 16; j++) { wts[j] = lg[j]; mx = fmaxf(mx, wts[j]); }
    float s = 0.f;
#pragma unroll
    for (int j = 0; j < 16; j++) { wts[j] = __expf(wts[j] - mx); s += wts[j]; }
    const float inv = 1.f / s;

    const float* offp = off + (size_t)bq * 256 + h * 32;  // [L][P][2]
    const float* rp = refp + (size_t)bq * 8;              // [L][2]

    float acc = 0.f;
#pragma unroll
    for (int l = 0; l < 4; l++) {
        const int D = dims[l];                 // H == W per level
        const float fD = (float)D;
        const float rx = rp[l * 2 + 0];
        const float ry = rp[l * 2 + 1];
        const float* vbase = v + (((size_t)b * LQ + start[l]) * HEADS + h) * 32 + c;
#pragma unroll
        for (int p = 0; p < 4; p++) {
            const float ox = offp[(l * 4 + p) * 2 + 0];
            const float oy = offp[(l * 4 + p) * 2 + 1];
            // gx = (ref + off/W)*W - 0.5
            const float gx = fmaf(rx, fD, ox) - 0.5f;
            const float gy = fmaf(ry, fD, oy) - 0.5f;
            const float x0f = floorf(gx);
            const float y0f = floorf(gy);
            const float wx = gx - x0f;
            const float wy = gy - y0f;
            const int x0 = (int)x0f, y0 = (int)y0f;
            const int x1 = x0 + 1, y1 = y0 + 1;

            float smp = 0.f;
            const bool vx0 = (x0 >= 0) & (x0 < D);
            const bool vx1 = (x1 >= 0) & (x1 < D);
            const bool vy0 = (y0 >= 0) & (y0 < D);
            const bool vy1 = (y1 >= 0) & (y1 < D);
            if (vy0) {
                const float* row = vbase + (size_t)y0 * D * 256;
                if (vx0) smp += (1.f - wx) * (1.f - wy) * row[(size_t)x0 * 256];
                if (vx1) smp += wx * (1.f - wy) * row[(size_t)x1 * 256];
            }
            if (vy1) {
                const float* row = vbase + (size_t)y1 * D * 256;
                if (vx0) smp += (1.f - wx) * wy * row[(size_t)x0 * 256];
                if (vx1) smp += wx * wy * row[(size_t)x1 * 256];
            }
            acc = fmaf(wts[l * 4 + p] * inv, smp, acc);
        }
    }
    out[(size_t)bq * 256 + h * 32 + c] = acc;
}

// ---------------- launch ----------------
extern "C" void kernel_launch(void* const* d_in, const int* in_sizes, int n_in,
                              void* d_out, int out_size)
{
    const float* query = (const float*)d_in[0];
    const float* refp  = (const float*)d_in[1];
    const float* value = (const float*)d_in[2];
    // d_in[3] = value_spatial_shapes (static, hardcoded)
    const float* W_off  = (const float*)d_in[4];
    const float* b_off  = (const float*)d_in[5];
    const float* W_attn = (const float*)d_in[6];
    const float* b_attn = (const float*)d_in[7];
    const float* W_val  = (const float*)d_in[8];
    const float* b_val  = (const float*)d_in[9];
    const float* W_out  = (const float*)d_in[10];
    const float* b_out  = (const float*)d_in[11];
    float* out = (float*)d_out;

    float *pv, *poff, *pattn, *pacc;
    cudaGetSymbolAddress((void**)&pv, g_v);
    cudaGetSymbolAddress((void**)&poff, g_off);
    cudaGetSymbolAddress((void**)&pattn, g_attn);
    cudaGetSymbolAddress((void**)&pacc, g_acc);

    const int M = MTOT;
    dim3 blk(256);
    dim3 grid256(256 / BN, (M + BM - 1) / BM);
    dim3 grid128(128 / BN, (M + BM - 1) / BM);

    // 1. v = value @ W_val + b_val
    gemm_bias_kernel<<<grid256, blk>>>(value, W_val, b_val, pv, M, 256, 256);
    // 2. off = query @ W_off + b_off
    gemm_bias_kernel<<<grid256, blk>>>(query, W_off, b_off, poff, M, 256, 256);
    // 3. attn logits = query @ W_attn + b_attn
    gemm_bias_kernel<<<grid128, blk>>>(query, W_attn, b_attn, pattn, M, 128, 256);
    // 4. softmax + bilinear sampling
    sample_kernel<<<M, blk>>>(refp, poff, pattn, pv, pacc);
    // 5. out = acc @ W_out + b_out
    gemm_bias_kernel<<<grid256, blk>>>(pacc, W_out, b_out, out, M, 256, 256);
}

// round 3
// speedup vs baseline: 1.3751x; 1.3751x over previous
#include <cuda_runtime.h>
#include <math.h>

#define BS 4
#define LQ 12240
#define EMBED 256
#define HEADS 8
#define MTOT (BS * LQ)   // 48960

// ---------------- scratch (no cudaMalloc allowed) ----------------
__device__ float g_v[(size_t)MTOT * 256];     // projected value [b,Lv,H,32]
__device__ float g_off[(size_t)MTOT * 256];   // offsets [b,q,H,L,P,2]
__device__ float g_attn[(size_t)MTOT * 128];  // attn logits [b,q,H,16]
__device__ float g_acc[(size_t)MTOT * 256];   // sampled acc [b,q,H,32]

// ---------------- fp32 tiled GEMM: C = A(MxK) @ B(KxN) + bias ----------------
#define BM 128
#define BN 64
#define BK 16

__global__ __launch_bounds__(256) void gemm_bias_kernel(
    const float* __restrict__ A, const float* __restrict__ B,
    const float* __restrict__ bias, float* __restrict__ C,
    int M, int N, int K)
{
    __shared__ float As[BK][BM + 4];
    __shared__ float Bs[BK][BN];

    const int tid = threadIdx.x;
    const int bm = blockIdx.y * BM;
    const int bn = blockIdx.x * BN;
    const int tm = (tid >> 4) * 8;   // 0..120
    const int tn = (tid & 15) * 4;   // 0..60

    float acc[8][4];
#pragma unroll
    for (int i = 0; i < 8; i++)
#pragma unroll
        for (int j = 0; j < 4; j++) acc[i][j] = 0.f;

    for (int k0 = 0; k0 < K; k0 += BK) {
#pragma unroll
        for (int r = 0; r < 2; r++) {
            int idx = tid + r * 256;          // 0..511
            int row = idx >> 2;               // 0..127
            int kc = (idx & 3) * 4;           // 0,4,8,12
            int grow = bm + row;
            if (grow >= M) grow = M - 1;      // clamp; C store is guarded
            float4 a = *(const float4*)&A[(size_t)grow * K + k0 + kc];
            As[kc + 0][row] = a.x;
            As[kc + 1][row] = a.y;
            As[kc + 2][row] = a.z;
            As[kc + 3][row] = a.w;
        }
        {
            int row = tid >> 4;               // 0..15
            int col = (tid & 15) * 4;         // 0..60
            *(float4*)&Bs[row][col] = *(const float4*)&B[(size_t)(k0 + row) * N + bn + col];
        }
        __syncthreads();

#pragma unroll
        for (int k = 0; k < BK; k++) {
            float a[8], bf[4];
#pragma unroll
            for (int i = 0; i < 8; i++) a[i] = As[k][tm + i];
#pragma unroll
            for (int j = 0; j < 4; j++) bf[j] = Bs[k][tn + j];
#pragma unroll
            for (int i = 0; i < 8; i++)
#pragma unroll
                for (int j = 0; j < 4; j++) acc[i][j] = fmaf(a[i], bf[j], acc[i][j]);
        }
        __syncthreads();
    }

    float4 bv = *(const float4*)&bias[bn + tn];
#pragma unroll
    for (int i = 0; i < 8; i++) {
        int m = bm + tm + i;
        if (m < M) {
            float4 o;
            o.x = acc[i][0] + bv.x;
            o.y = acc[i][1] + bv.y;
            o.z = acc[i][2] + bv.z;
            o.w = acc[i][3] + bv.w;
            *(float4*)&C[(size_t)m * N + bn + tn] = o;
        }
    }
}

// ---------------- softmax + bilinear sampling ----------------
// block = (b,q); warp = head. All 32 lanes compute per-point (j = lane&15)
// corner offsets + premultiplied weights (lanes 16..31 duplicate); lanes
// 0..15 write them to smem; then all 32 lanes gather channels.
__global__ __launch_bounds__(256) void sample_kernel(
    const float* __restrict__ refp,   // [BS,LQ,4,2]
    const float* __restrict__ off,    // [BS*LQ, 256] = [H][L][P][2]
    const float* __restrict__ logits, // [BS*LQ, 128] = [H][16]
    const float* __restrict__ v,      // [BS,LQ,8,32]
    float* __restrict__ out)          // [BS*LQ, 256]
{
    __shared__ int4   s_off[HEADS][16];
    __shared__ float4 s_w[HEADS][16];

    const int bq = blockIdx.x;
    const int b = bq / LQ;
    const int h = threadIdx.x >> 5;
    const int lane = threadIdx.x & 31;
    const int j = lane & 15;          // (level,point) index

    // ---- softmax over 16 logits: width-16 shfl, all lanes participate ----
    const float* lg = logits + (size_t)bq * 128 + h * 16;
    float logit = lg[j];
    float mx = logit;
#pragma unroll
    for (int k = 8; k >= 1; k >>= 1)
        mx = fmaxf(mx, __shfl_xor_sync(0xffffffffu, mx, k, 16));
    float e = __expf(logit - mx);
    float s = e;
#pragma unroll
    for (int k = 8; k >= 1; k >>= 1)
        s += __shfl_xor_sync(0xffffffffu, s, k, 16);
    const float aw = e / s;   // attention weight for this (level,point)

    // ---- coordinates for point j ----
    const int l = j >> 2;
    const int D = 96 >> l;                        // level dims (H==W)
    const int start = 12288 - (12288 >> (2 * l)); // level start row
    const float fD = (float)D;

    const float2 r2 = ((const float2*)(refp + (size_t)bq * 8))[l];
    const float2 o2 = ((const float2*)(off + (size_t)bq * 256 + h * 32))[j];

    const float gx = fmaf(r2.x, fD, o2.x) - 0.5f;
    const float gy = fmaf(r2.y, fD, o2.y) - 0.5f;
    const float x0f = floorf(gx);
    const float y0f = floorf(gy);
    const float wx = gx - x0f;
    const float wy = gy - y0f;
    const int x0 = (int)x0f, y0 = (int)y0f;
    const int x1 = x0 + 1, y1 = y0 + 1;

    const bool vx0 = (x0 >= 0) & (x0 < D);
    const bool vx1 = (x1 >= 0) & (x1 < D);
    const bool vy0 = (y0 >= 0) & (y0 < D);
    const bool vy1 = (y1 >= 0) & (y1 < D);

    int4 o4;
    float4 w4;
    o4.x = (vx0 & vy0) ? (start + y0 * D + x0) * 256 : 0;
    o4.y = (vx1 & vy0) ? (start + y0 * D + x1) * 256 : 0;
    o4.z = (vx0 & vy1) ? (start + y1 * D + x0) * 256 : 0;
    o4.w = (vx1 & vy1) ? (start + y1 * D + x1) * 256 : 0;
    w4.x = (vx0 & vy0) ? (1.f - wx) * (1.f - wy) * aw : 0.f;
    w4.y = (vx1 & vy0) ? wx * (1.f - wy) * aw : 0.f;
    w4.z = (vx0 & vy1) ? (1.f - wx) * wy * aw : 0.f;
    w4.w = (vx1 & vy1) ? wx * wy * aw : 0.f;

    if (lane < 16) {
        s_off[h][j] = o4;
        s_w[h][j] = w4;
    }
    __syncwarp();

    // ---- gather: lane = channel ----
    const float* __restrict__ vb = v + (size_t)b * LQ * 256 + h * 32 + lane;
    float acc = 0.f;
#pragma unroll
    for (int p = 0; p < 16; p++) {
        const int4 o = s_off[h][p];
        const float4 w = s_w[h][p];
        acc = fmaf(w.x, __ldg(vb + o.x), acc);
        acc = fmaf(w.y, __ldg(vb + o.y), acc);
        acc = fmaf(w.z, __ldg(vb + o.z), acc);
        acc = fmaf(w.w, __ldg(vb + o.w), acc);
    }
    out[(size_t)bq * 256 + h * 32 + lane] = acc;
}

// ---------------- launch ----------------
extern "C" void kernel_launch(void* const* d_in, const int* in_sizes, int n_in,
                              void* d_out, int out_size)
{
    const float* query = (const float*)d_in[0];
    const float* refp  = (const float*)d_in[1];
    const float* value = (const float*)d_in[2];
    // d_in[3] = value_spatial_shapes (static, hardcoded)
    const float* W_off  = (const float*)d_in[4];
    const float* b_off  = (const float*)d_in[5];
    const float* W_attn = (const float*)d_in[6];
    const float* b_attn = (const float*)d_in[7];
    const float* W_val  = (const float*)d_in[8];
    const float* b_val  = (const float*)d_in[9];
    const float* W_out  = (const float*)d_in[10];
    const float* b_out  = (const float*)d_in[11];
    float* out = (float*)d_out;

    float *pv, *poff, *pattn, *pacc;
    cudaGetSymbolAddress((void**)&pv, g_v);
    cudaGetSymbolAddress((void**)&poff, g_off);
    cudaGetSymbolAddress((void**)&pattn, g_attn);
    cudaGetSymbolAddress((void**)&pacc, g_acc);

    const int M = MTOT;
    dim3 blk(256);
    dim3 grid256(256 / BN, (M + BM - 1) / BM);
    dim3 grid128(128 / BN, (M + BM - 1) / BM);

    gemm_bias_kernel<<<grid256, blk>>>(value, W_val, b_val, pv, M, 256, 256);
    gemm_bias_kernel<<<grid256, blk>>>(query, W_off, b_off, poff, M, 256, 256);
    gemm_bias_kernel<<<grid128, blk>>>(query, W_attn, b_attn, pattn, M, 128, 256);
    sample_kernel<<<M, blk>>>(refp, poff, pattn, pv, pacc);
    gemm_bias_kernel<<<grid256, blk>>>(pacc, W_out, b_out, out, M, 256, 256);
}

// round 5
// speedup vs baseline: 1.3941x; 1.0138x over previous
#include <cuda_runtime.h>
#include <cstdint>
#include <math.h>

#define BS 4
#define LQ 12240
#define EMBED 256
#define HEADS 8
#define MTOT (BS * LQ)   // 48960

// ---------------- scratch (no cudaMalloc allowed) ----------------
__device__ float g_v[(size_t)MTOT * 256];     // projected value [b,Lv,H,32]
__device__ float g_off[(size_t)MTOT * 256];   // offsets [b,q,H,L,P,2]
__device__ float g_attn[(size_t)MTOT * 128];  // attn logits [b,q,H,16]
__device__ float g_acc[(size_t)MTOT * 256];   // sampled acc [b,q,H,32]

// ---------------- tf32 split-precision tensor-core GEMM ----------------
// C[M,N] = A[M,K] @ B[K,N] + bias.  K=256 multiple of 16, N multiple of 64.
// Block tile 128x64, 8 warps as 4(M) x 2(N), each warp 32x32 = 2x4 m16n8 tiles.
// Precision: a = hi + lo (tf32 split); D = Ahi*Bhi + Ahi*Blo + Alo*Bhi.

__device__ __forceinline__ void split_tf32(float x, uint32_t& hi, uint32_t& lo) {
    uint32_t h;
    asm("cvt.rna.tf32.f32 %0, %1;" : "=r"(h) : "f"(x));
    float l = x - __uint_as_float(h);
    uint32_t lw;
    asm("cvt.rna.tf32.f32 %0, %1;" : "=r"(lw) : "f"(l));
    hi = h; lo = lw;
}

__device__ __forceinline__ void mma_tf32(float* d, const uint32_t* a, const uint32_t* b) {
    asm volatile(
        "mma.sync.aligned.m16n8k8.row.col.f32.tf32.tf32.f32 "
        "{%0,%1,%2,%3}, {%4,%5,%6,%7}, {%8,%9}, {%0,%1,%2,%3};"
        : "+f"(d[0]), "+f"(d[1]), "+f"(d[2]), "+f"(d[3])
        : "r"(a[0]), "r"(a[1]), "r"(a[2]), "r"(a[3]), "r"(b[0]), "r"(b[1]));
}

__global__ __launch_bounds__(256) void gemm_tf32_kernel(
    const float* __restrict__ A, const float* __restrict__ B,
    const float* __restrict__ bias, float* __restrict__ C,
    int M, int N, int K)
{
    __shared__ float As[16][132];  // [k][m], padded
    __shared__ float Bs[16][68];   // [k][n], padded

    const int tid = threadIdx.x;
    const int bm = blockIdx.y * 128;
    const int bn = blockIdx.x * 64;
    const int warp = tid >> 5;
    const int lane = tid & 31;
    const int wm = (warp >> 1) * 32;   // warp M offset in tile
    const int wn = (warp & 1) * 32;    // warp N offset in tile
    const int g = lane >> 2;           // 0..7
    const int tig = lane & 3;          // 0..3

    float acc[2][4][4];
#pragma unroll
    for (int i = 0; i < 2; i++)
#pragma unroll
        for (int j = 0; j < 4; j++)
#pragma unroll
            for (int r = 0; r < 4; r++) acc[i][j][r] = 0.f;

    for (int k0 = 0; k0 < K; k0 += 16) {
        // load A tile 128x16, transposed into As[k][m]
#pragma unroll
        for (int r = 0; r < 2; r++) {
            int idx = tid + r * 256;          // 0..511
            int row = idx >> 2;               // 0..127
            int kc = (idx & 3) * 4;           // 0,4,8,12
            int grow = bm + row;
            if (grow >= M) grow = M - 1;
            float4 a = *(const float4*)&A[(size_t)grow * K + k0 + kc];
            As[kc + 0][row] = a.x;
            As[kc + 1][row] = a.y;
            As[kc + 2][row] = a.z;
            As[kc + 3][row] = a.w;
        }
        // load B tile 16x64
        {
            int row = tid >> 4;               // 0..15
            int col = (tid & 15) * 4;         // 0..60
            float4 bv = *(const float4*)&B[(size_t)(k0 + row) * N + bn + col];
            Bs[row][col + 0] = bv.x;
            Bs[row][col + 1] = bv.y;
            Bs[row][col + 2] = bv.z;
            Bs[row][col + 3] = bv.w;
        }
        __syncthreads();

#pragma unroll
        for (int ks = 0; ks < 2; ks++) {
            const int k8 = ks * 8;
            // A fragments for 2 m16 tiles
            uint32_t ahi[2][4], alo[2][4];
#pragma unroll
            for (int mt = 0; mt < 2; mt++) {
                const int mb = wm + mt * 16;
                split_tf32(As[k8 + tig][mb + g],         ahi[mt][0], alo[mt][0]);
                split_tf32(As[k8 + tig][mb + g + 8],     ahi[mt][1], alo[mt][1]);
                split_tf32(As[k8 + tig + 4][mb + g],     ahi[mt][2], alo[mt][2]);
                split_tf32(As[k8 + tig + 4][mb + g + 8], ahi[mt][3], alo[mt][3]);
            }
            // B fragments for 4 n8 tiles
            uint32_t bhi[4][2], blo[4][2];
#pragma unroll
            for (int nt = 0; nt < 4; nt++) {
                const int nb = wn + nt * 8;
                split_tf32(Bs[k8 + tig][nb + g],     bhi[nt][0], blo[nt][0]);
                split_tf32(Bs[k8 + tig + 4][nb + g], bhi[nt][1], blo[nt][1]);
            }
#pragma unroll
            for (int mt = 0; mt < 2; mt++)
#pragma unroll
                for (int nt = 0; nt < 4; nt++) {
                    mma_tf32(acc[mt][nt], ahi[mt], bhi[nt]);
                    mma_tf32(acc[mt][nt], ahi[mt], blo[nt]);
                    mma_tf32(acc[mt][nt], alo[mt], bhi[nt]);
                }
        }
        __syncthreads();
    }

    // epilogue: D + bias -> C
#pragma unroll
    for (int nt = 0; nt < 4; nt++) {
        const int n = bn + wn + nt * 8 + 2 * tig;
        const float b0 = bias[n];
        const float b1 = bias[n + 1];
#pragma unroll
        for (int mt = 0; mt < 2; mt++) {
            const int m0 = bm + wm + mt * 16 + g;
            if (m0 < M) {
                float2 o = make_float2(acc[mt][nt][0] + b0, acc[mt][nt][1] + b1);
                *(float2*)&C[(size_t)m0 * N + n] = o;
            }
            const int m1 = m0 + 8;
            if (m1 < M) {
                float2 o = make_float2(acc[mt][nt][2] + b0, acc[mt][nt][3] + b1);
                *(float2*)&C[(size_t)m1 * N + n] = o;
            }
        }
    }
}

// ---------------- softmax + bilinear sampling ----------------
__global__ __launch_bounds__(256) void sample_kernel(
    const float* __restrict__ refp,   // [BS,LQ,4,2]
    const float* __restrict__ off,    // [BS*LQ, 256] = [H][L][P][2]
    const float* __restrict__ logits, // [BS*LQ, 128] = [H][16]
    const float* __restrict__ v,      // [BS,LQ,8,32]
    float* __restrict__ out)          // [BS*LQ, 256]
{
    __shared__ int4   s_off[HEADS][16];
    __shared__ float4 s_w[HEADS][16];

    const int bq = blockIdx.x;
    const int b = bq / LQ;
    const int h = threadIdx.x >> 5;
    const int lane = threadIdx.x & 31;
    const int j = lane & 15;          // (level,point) index

    const float* lg = logits + (size_t)bq * 128 + h * 16;
    float logit = lg[j];
    float mx = logit;
#pragma unroll
    for (int k = 8; k >= 1; k >>= 1)
        mx = fmaxf(mx, __shfl_xor_sync(0xffffffffu, mx, k, 16));
    float e = __expf(logit - mx);
    float s = e;
#pragma unroll
    for (int k = 8; k >= 1; k >>= 1)
        s += __shfl_xor_sync(0xffffffffu, s, k, 16);
    const float aw = e / s;

    const int l = j >> 2;
    const int D = 96 >> l;
    const int start = 12288 - (12288 >> (2 * l));
    const float fD = (float)D;

    const float2 r2 = ((const float2*)(refp + (size_t)bq * 8))[l];
    const float2 o2 = ((const float2*)(off + (size_t)bq * 256 + h * 32))[j];

    const float gx = fmaf(r2.x, fD, o2.x) - 0.5f;
    const float gy = fmaf(r2.y, fD, o2.y) - 0.5f;
    const float x0f = floorf(gx);
    const float y0f = floorf(gy);
    const float wx = gx - x0f;
    const float wy = gy - y0f;
    const int x0 = (int)x0f, y0 = (int)y0f;
    const int x1 = x0 + 1, y1 = y0 + 1;

    const bool vx0 = (x0 >= 0) & (x0 < D);
    const bool vx1 = (x1 >= 0) & (x1 < D);
    const bool vy0 = (y0 >= 0) & (y0 < D);
    const bool vy1 = (y1 >= 0) & (y1 < D);

    int4 o4;
    float4 w4;
    o4.x = (vx0 & vy0) ? (start + y0 * D + x0) * 256 : 0;
    o4.y = (vx1 & vy0) ? (start + y0 * D + x1) * 256 : 0;
    o4.z = (vx0 & vy1) ? (start + y1 * D + x0) * 256 : 0;
    o4.w = (vx1 & vy1) ? (start + y1 * D + x1) * 256 : 0;
    w4.x = (vx0 & vy0) ? (1.f - wx) * (1.f - wy) * aw : 0.f;
    w4.y = (vx1 & vy0) ? wx * (1.f - wy) * aw : 0.f;
    w4.z = (vx0 & vy1) ? (1.f - wx) * wy * aw : 0.f;
    w4.w = (vx1 & vy1) ? wx * wy * aw : 0.f;

    if (lane < 16) {
        s_off[h][j] = o4;
        s_w[h][j] = w4;
    }
    __syncwarp();

    const float* __restrict__ vb = v + (size_t)b * LQ * 256 + h * 32 + lane;
    float acc = 0.f;
#pragma unroll
    for (int p = 0; p < 16; p++) {
        const int4 o = s_off[h][p];
        const float4 w = s_w[h][p];
        acc = fmaf(w.x, __ldg(vb + o.x), acc);
        acc = fmaf(w.y, __ldg(vb + o.y), acc);
        acc = fmaf(w.z, __ldg(vb + o.z), acc);
        acc = fmaf(w.w, __ldg(vb + o.w), acc);
    }
    out[(size_t)bq * 256 + h * 32 + lane] = acc;
}

// ---------------- launch ----------------
extern "C" void kernel_launch(void* const* d_in, const int* in_sizes, int n_in,
                              void* d_out, int out_size)
{
    const float* query = (const float*)d_in[0];
    const float* refp  = (const float*)d_in[1];
    const float* value = (const float*)d_in[2];
    // d_in[3] = value_spatial_shapes (static, hardcoded)
    const float* W_off  = (const float*)d_in[4];
    const float* b_off  = (const float*)d_in[5];
    const float* W_attn = (const float*)d_in[6];
    const float* b_attn = (const float*)d_in[7];
    const float* W_val  = (const float*)d_in[8];
    const float* b_val  = (const float*)d_in[9];
    const float* W_out  = (const float*)d_in[10];
    const float* b_out  = (const float*)d_in[11];
    float* out = (float*)d_out;

    float *pv, *poff, *pattn, *pacc;
    cudaGetSymbolAddress((void**)&pv, g_v);
    cudaGetSymbolAddress((void**)&poff, g_off);
    cudaGetSymbolAddress((void**)&pattn, g_attn);
    cudaGetSymbolAddress((void**)&pacc, g_acc);

    const int M = MTOT;
    dim3 blk(256);
    dim3 grid256(256 / 64, (M + 127) / 128);
    dim3 grid128(128 / 64, (M + 127) / 128);

    gemm_tf32_kernel<<<grid256, blk>>>(value, W_val, b_val, pv, M, 256, 256);
    gemm_tf32_kernel<<<grid256, blk>>>(query, W_off, b_off, poff, M, 256, 256);
    gemm_tf32_kernel<<<grid128, blk>>>(query, W_attn, b_attn, pattn, M, 128, 256);
    sample_kernel<<<M, blk>>>(refp, poff, pattn, pv, pacc);
    gemm_tf32_kernel<<<grid256, blk>>>(pacc, W_out, b_out, out, M, 256, 256);
}

// round 6
// speedup vs baseline: 1.9664x; 1.4105x over previous
#include <cuda_runtime.h>
#include <cstdint>
#include <math.h>

#define BS 4
#define LQ 12240
#define EMBED 256
#define HEADS 8
#define MTOT (BS * LQ)   // 48960

// ---------------- scratch (no cudaMalloc allowed) ----------------
__device__ float g_v[(size_t)MTOT * 256];     // projected value [b,Lv,H,32]
__device__ float g_off[(size_t)MTOT * 256];   // offsets [b,q,H,L,P,2]
__device__ float g_attn[(size_t)MTOT * 128];  // attn logits [b,q,H,16]
__device__ float g_acc[(size_t)MTOT * 256];   // sampled acc [b,q,H,32]

// ---------------- tf32 tensor-core GEMM (single-term) ----------------
// C[M,N] = A[M,K] @ B[K,N] + bias.  K mult of 16, N mult of 64.
// Block tile 128x64, 8 warps as 4(M) x 2(N), each warp 32x32 = 2x4 m16n8 tiles.
// fp32 -> tf32 conversion happens ONCE per element at smem-store time.

__device__ __forceinline__ uint32_t to_tf32(float x) {
    uint32_t h;
    asm("cvt.rna.tf32.f32 %0, %1;" : "=r"(h) : "f"(x));
    return h;
}

__device__ __forceinline__ void mma_tf32(float* d, const uint32_t* a, const uint32_t* b) {
    asm volatile(
        "mma.sync.aligned.m16n8k8.row.col.f32.tf32.tf32.f32 "
        "{%0,%1,%2,%3}, {%4,%5,%6,%7}, {%8,%9}, {%0,%1,%2,%3};"
        : "+f"(d[0]), "+f"(d[1]), "+f"(d[2]), "+f"(d[3])
        : "r"(a[0]), "r"(a[1]), "r"(a[2]), "r"(a[3]), "r"(b[0]), "r"(b[1]));
}

__global__ __launch_bounds__(256) void gemm_tf32_kernel(
    const float* __restrict__ A, const float* __restrict__ B,
    const float* __restrict__ bias, float* __restrict__ C,
    int M, int N, int K)
{
    __shared__ uint32_t As[16][132];  // [k][m] tf32, padded
    __shared__ uint32_t Bs[16][68];   // [k][n] tf32, padded

    const int tid = threadIdx.x;
    const int bm = blockIdx.y * 128;
    const int bn = blockIdx.x * 64;
    const int warp = tid >> 5;
    const int lane = tid & 31;
    const int wm = (warp >> 1) * 32;   // warp M offset in tile
    const int wn = (warp & 1) * 32;    // warp N offset in tile
    const int g = lane >> 2;           // 0..7
    const int tig = lane & 3;          // 0..3

    float acc[2][4][4];
#pragma unroll
    for (int i = 0; i < 2; i++)
#pragma unroll
        for (int j = 0; j < 4; j++)
#pragma unroll
            for (int r = 0; r < 4; r++) acc[i][j][r] = 0.f;

    for (int k0 = 0; k0 < K; k0 += 16) {
        // load A tile 128x16, convert to tf32, transpose into As[k][m]
#pragma unroll
        for (int r = 0; r < 2; r++) {
            int idx = tid + r * 256;          // 0..511
            int row = idx >> 2;               // 0..127
            int kc = (idx & 3) * 4;           // 0,4,8,12
            int grow = bm + row;
            if (grow >= M) grow = M - 1;
            float4 a = *(const float4*)&A[(size_t)grow * K + k0 + kc];
            As[kc + 0][row] = to_tf32(a.x);
            As[kc + 1][row] = to_tf32(a.y);
            As[kc + 2][row] = to_tf32(a.z);
            As[kc + 3][row] = to_tf32(a.w);
        }
        // load B tile 16x64, convert to tf32
        {
            int row = tid >> 4;               // 0..15
            int col = (tid & 15) * 4;         // 0..60
            float4 bv = *(const float4*)&B[(size_t)(k0 + row) * N + bn + col];
            Bs[row][col + 0] = to_tf32(bv.x);
            Bs[row][col + 1] = to_tf32(bv.y);
            Bs[row][col + 2] = to_tf32(bv.z);
            Bs[row][col + 3] = to_tf32(bv.w);
        }
        __syncthreads();

#pragma unroll
        for (int ks = 0; ks < 2; ks++) {
            const int k8 = ks * 8;
            uint32_t af[2][4];
#pragma unroll
            for (int mt = 0; mt < 2; mt++) {
                const int mb = wm + mt * 16;
                af[mt][0] = As[k8 + tig][mb + g];
                af[mt][1] = As[k8 + tig][mb + g + 8];
                af[mt][2] = As[k8 + tig + 4][mb + g];
                af[mt][3] = As[k8 + tig + 4][mb + g + 8];
            }
            uint32_t bf[4][2];
#pragma unroll
            for (int nt = 0; nt < 4; nt++) {
                const int nb = wn + nt * 8;
                bf[nt][0] = Bs[k8 + tig][nb + g];
                bf[nt][1] = Bs[k8 + tig + 4][nb + g];
            }
#pragma unroll
            for (int mt = 0; mt < 2; mt++)
#pragma unroll
                for (int nt = 0; nt < 4; nt++)
                    mma_tf32(acc[mt][nt], af[mt], bf[nt]);
        }
        __syncthreads();
    }

    // epilogue: D + bias -> C
#pragma unroll
    for (int nt = 0; nt < 4; nt++) {
        const int n = bn + wn + nt * 8 + 2 * tig;
        const float b0 = bias[n];
        const float b1 = bias[n + 1];
#pragma unroll
        for (int mt = 0; mt < 2; mt++) {
            const int m0 = bm + wm + mt * 16 + g;
            if (m0 < M) {
                float2 o = make_float2(acc[mt][nt][0] + b0, acc[mt][nt][1] + b1);
                *(float2*)&C[(size_t)m0 * N + n] = o;
            }
            const int m1 = m0 + 8;
            if (m1 < M) {
                float2 o = make_float2(acc[mt][nt][2] + b0, acc[mt][nt][3] + b1);
                *(float2*)&C[(size_t)m1 * N + n] = o;
            }
        }
    }
}

// ---------------- softmax + bilinear sampling ----------------
__global__ __launch_bounds__(256) void sample_kernel(
    const float* __restrict__ refp,   // [BS,LQ,4,2]
    const float* __restrict__ off,    // [BS*LQ, 256] = [H][L][P][2]
    const float* __restrict__ logits, // [BS*LQ, 128] = [H][16]
    const float* __restrict__ v,      // [BS,LQ,8,32]
    float* __restrict__ out)          // [BS*LQ, 256]
{
    __shared__ int4   s_off[HEADS][16];
    __shared__ float4 s_w[HEADS][16];

    const int bq = blockIdx.x;
    const int b = bq / LQ;
    const int h = threadIdx.x >> 5;
    const int lane = threadIdx.x & 31;
    const int j = lane & 15;          // (level,point) index

    const float* lg = logits + (size_t)bq * 128 + h * 16;
    float logit = lg[j];
    float mx = logit;
#pragma unroll
    for (int k = 8; k >= 1; k >>= 1)
        mx = fmaxf(mx, __shfl_xor_sync(0xffffffffu, mx, k, 16));
    float e = __expf(logit - mx);
    float s = e;
#pragma unroll
    for (int k = 8; k >= 1; k >>= 1)
        s += __shfl_xor_sync(0xffffffffu, s, k, 16);
    const float aw = e / s;

    const int l = j >> 2;
    const int D = 96 >> l;
    const int start = 12288 - (12288 >> (2 * l));
    const float fD = (float)D;

    const float2 r2 = ((const float2*)(refp + (size_t)bq * 8))[l];
    const float2 o2 = ((const float2*)(off + (size_t)bq * 256 + h * 32))[j];

    const float gx = fmaf(r2.x, fD, o2.x) - 0.5f;
    const float gy = fmaf(r2.y, fD, o2.y) - 0.5f;
    const float x0f = floorf(gx);
    const float y0f = floorf(gy);
    const float wx = gx - x0f;
    const float wy = gy - y0f;
    const int x0 = (int)x0f, y0 = (int)y0f;
    const int x1 = x0 + 1, y1 = y0 + 1;

    const bool vx0 = (x0 >= 0) & (x0 < D);
    const bool vx1 = (x1 >= 0) & (x1 < D);
    const bool vy0 = (y0 >= 0) & (y0 < D);
    const bool vy1 = (y1 >= 0) & (y1 < D);

    int4 o4;
    float4 w4;
    o4.x = (vx0 & vy0) ? (start + y0 * D + x0) * 256 : 0;
    o4.y = (vx1 & vy0) ? (start + y0 * D + x1) * 256 : 0;
    o4.z = (vx0 & vy1) ? (start + y1 * D + x0) * 256 : 0;
    o4.w = (vx1 & vy1) ? (start + y1 * D + x1) * 256 : 0;
    w4.x = (vx0 & vy0) ? (1.f - wx) * (1.f - wy) * aw : 0.f;
    w4.y = (vx1 & vy0) ? wx * (1.f - wy) * aw : 0.f;
    w4.z = (vx0 & vy1) ? (1.f - wx) * wy * aw : 0.f;
    w4.w = (vx1 & vy1) ? wx * wy * aw : 0.f;

    if (lane < 16) {
        s_off[h][j] = o4;
        s_w[h][j] = w4;
    }
    __syncwarp();

    const float* __restrict__ vb = v + (size_t)b * LQ * 256 + h * 32 + lane;
    float acc = 0.f;
#pragma unroll
    for (int p = 0; p < 16; p++) {
        const int4 o = s_off[h][p];
        const float4 w = s_w[h][p];
        acc = fmaf(w.x, __ldg(vb + o.x), acc);
        acc = fmaf(w.y, __ldg(vb + o.y), acc);
        acc = fmaf(w.z, __ldg(vb + o.z), acc);
        acc = fmaf(w.w, __ldg(vb + o.w), acc);
    }
    out[(size_t)bq * 256 + h * 32 + lane] = acc;
}

// ---------------- launch ----------------
extern "C" void kernel_launch(void* const* d_in, const int* in_sizes, int n_in,
                              void* d_out, int out_size)
{
    const float* query = (const float*)d_in[0];
    const float* refp  = (const float*)d_in[1];
    const float* value = (const float*)d_in[2];
    // d_in[3] = value_spatial_shapes (static, hardcoded)
    const float* W_off  = (const float*)d_in[4];
    const float* b_off  = (const float*)d_in[5];
    const float* W_attn = (const float*)d_in[6];
    const float* b_attn = (const float*)d_in[7];
    const float* W_val  = (const float*)d_in[8];
    const float* b_val  = (const float*)d_in[9];
    const float* W_out  = (const float*)d_in[10];
    const float* b_out  = (const float*)d_in[11];
    float* out = (float*)d_out;

    float *pv, *poff, *pattn, *pacc;
    cudaGetSymbolAddress((void**)&pv, g_v);
    cudaGetSymbolAddress((void**)&poff, g_off);
    cudaGetSymbolAddress((void**)&pattn, g_attn);
    cudaGetSymbolAddress((void**)&pacc, g_acc);

    const int M = MTOT;
    dim3 blk(256);
    dim3 grid256(256 / 64, (M + 127) / 128);
    dim3 grid128(128 / 64, (M + 127) / 128);

    gemm_tf32_kernel<<<grid256, blk>>>(value, W_val, b_val, pv, M, 256, 256);
    gemm_tf32_kernel<<<grid256, blk>>>(query, W_off, b_off, poff, M, 256, 256);
    gemm_tf32_kernel<<<grid128, blk>>>(query, W_attn, b_attn, pattn, M, 128, 256);
    sample_kernel<<<M, blk>>>(refp, poff, pattn, pv, pacc);
    gemm_tf32_kernel<<<grid256, blk>>>(pacc, W_out, b_out, out, M, 256, 256);
}